// round 2
// baseline (speedup 1.0000x reference)
#include <cuda_runtime.h>
#include <stdint.h>

// Sort_Latent_Layer: z (B, 1, 8192) fp32. Per row: 512 packets of 16 floats,
// stable-sort packets by packet[0] ascending, gather, write back.
//
// One CTA per row, 512 threads (1 thread per packet).
//  - Stage row in smem as float4, padded 1 float4 per packet (5 float4 slots)
//    -> conflict-free linear stores, good gather reads.
//  - Keys extracted during staging (w==0 lane of each packet).
//  - Key packed to sortable u64: monotone uint32 of float in high bits,
//    original index in low bits -> unique items, tie-break = stable sort.
//  - Bitonic sort: distances j>=32 via smem, j<32 via __shfl_xor_sync.
//  - Gather from smem, coalesced float4 writes.

#define NPK   512   // packets per row
#define DPAD  5     // float4 slots per packet (4 data + 1 pad)

__global__ void __launch_bounds__(512, 1)
sort_latent_kernel(const float* __restrict__ z, float* __restrict__ out)
{
    __shared__ float4             sdata[NPK * DPAD];   // 40 KB
    __shared__ unsigned long long ssort[NPK];          //  4 KB
    __shared__ uint32_t           skeys[NPK];          //  2 KB (keys, then inds)

    const int tid = threadIdx.x;
    const long long row = blockIdx.x;
    const float4* __restrict__ in4 = (const float4*)(z + row * 8192);

    // ---- stage row into smem, harvest keys ----
    #pragma unroll
    for (int it = 0; it < 4; ++it) {
        int f = tid + it * 512;          // float4 index within row, 0..2047
        float4 v = in4[f];
        int p = f >> 2, w = f & 3;
        sdata[p * DPAD + w] = v;
        if (w == 0) skeys[p] = __float_as_uint(v.x);
    }
    __syncthreads();

    // ---- build sortable item ----
    uint32_t kb = skeys[tid];
    kb = (kb & 0x80000000u) ? ~kb : (kb | 0x80000000u);   // monotone float->uint
    unsigned long long item =
        ((unsigned long long)kb << 32) | (unsigned long long)(uint32_t)tid;

    // ---- bitonic sort, 512 items, ascending ----
    #pragma unroll 1
    for (int k = 2; k <= 512; k <<= 1) {
        const bool dir_up = ((tid & k) == 0);

        // cross-warp stages via smem
        #pragma unroll 1
        for (int j = k >> 1; j >= 32; j >>= 1) {
            __syncthreads();             // protect prior reads of ssort
            ssort[tid] = item;
            __syncthreads();
            unsigned long long other = ssort[tid ^ j];
            bool keep_min = (((tid & j) == 0) == dir_up);
            if ((other < item) == keep_min) item = other;
        }

        // intra-warp stages via shfl
        int jstart = (k >> 1) < 16 ? (k >> 1) : 16;
        #pragma unroll 1
        for (int j = jstart; j >= 1; j >>= 1) {
            unsigned long long other = __shfl_xor_sync(0xFFFFFFFFu, item, j);
            bool keep_min = (((tid & j) == 0) == dir_up);
            if ((other < item) == keep_min) item = other;
        }
    }

    // ---- publish permutation ----
    __syncthreads();
    skeys[tid] = (uint32_t)(item & 0xFFFFFFFFu);   // inds[tid] = source packet
    __syncthreads();

    // ---- gather from smem, coalesced write ----
    float4* __restrict__ out4 = (float4*)(out + row * 8192);
    #pragma unroll
    for (int it = 0; it < 4; ++it) {
        int f = tid + it * 512;
        int p = f >> 2, w = f & 3;
        int src = (int)skeys[p];
        out4[f] = sdata[src * DPAD + w];
    }
}

extern "C" void kernel_launch(void* const* d_in, const int* in_sizes, int n_in,
                              void* d_out, int out_size)
{
    const float* z  = (const float*)d_in[0];
    float* out      = (float*)d_out;
    const int D = 8192;                 // n_packets(512) * packet(16)
    int B = in_sizes[0] / D;            // 4096
    sort_latent_kernel<<<B, 512>>>(z, out);
}

// round 3
// speedup vs baseline: 1.0084x; 1.0084x over previous
#include <cuda_runtime.h>
#include <stdint.h>

// Sort_Latent_Layer: z (B, 1, 8192) fp32. Per row: 512 packets of 16 floats,
// stable-sort packets by packet[0] ascending, gather, write back.
//
// One CTA per row, 512 threads (1 thread per packet).
//  - Stage row in smem as float4, padded 1 float4 per packet (5 float4 slots)
//    -> conflict-free linear stores, good gather reads.
//  - Keys extracted during staging (w==0 lane of each packet).
//  - Key packed to sortable u64: monotone uint32 of float in high bits,
//    original index in low bits -> unique items, tie-break = stable sort.
//  - Bitonic sort: distances j>=32 via smem, j<32 via __shfl_xor_sync.
//  - Gather from smem, coalesced float4 writes.

#define NPK   512   // packets per row
#define DPAD  5     // float4 slots per packet (4 data + 1 pad)

__global__ void __launch_bounds__(512, 1)
sort_latent_kernel(const float* __restrict__ z, float* __restrict__ out)
{
    __shared__ float4             sdata[NPK * DPAD];   // 40 KB
    __shared__ unsigned long long ssort[NPK];          //  4 KB
    __shared__ uint32_t           skeys[NPK];          //  2 KB (keys, then inds)

    const int tid = threadIdx.x;
    const long long row = blockIdx.x;
    const float4* __restrict__ in4 = (const float4*)(z + row * 8192);

    // ---- stage row into smem, harvest keys ----
    #pragma unroll
    for (int it = 0; it < 4; ++it) {
        int f = tid + it * 512;          // float4 index within row, 0..2047
        float4 v = in4[f];
        int p = f >> 2, w = f & 3;
        sdata[p * DPAD + w] = v;
        if (w == 0) skeys[p] = __float_as_uint(v.x);
    }
    __syncthreads();

    // ---- build sortable item ----
    uint32_t kb = skeys[tid];
    kb = (kb & 0x80000000u) ? ~kb : (kb | 0x80000000u);   // monotone float->uint
    unsigned long long item =
        ((unsigned long long)kb << 32) | (unsigned long long)(uint32_t)tid;

    // ---- bitonic sort, 512 items, ascending ----
    #pragma unroll 1
    for (int k = 2; k <= 512; k <<= 1) {
        const bool dir_up = ((tid & k) == 0);

        // cross-warp stages via smem
        #pragma unroll 1
        for (int j = k >> 1; j >= 32; j >>= 1) {
            __syncthreads();             // protect prior reads of ssort
            ssort[tid] = item;
            __syncthreads();
            unsigned long long other = ssort[tid ^ j];
            bool keep_min = (((tid & j) == 0) == dir_up);
            if ((other < item) == keep_min) item = other;
        }

        // intra-warp stages via shfl
        int jstart = (k >> 1) < 16 ? (k >> 1) : 16;
        #pragma unroll 1
        for (int j = jstart; j >= 1; j >>= 1) {
            unsigned long long other = __shfl_xor_sync(0xFFFFFFFFu, item, j);
            bool keep_min = (((tid & j) == 0) == dir_up);
            if ((other < item) == keep_min) item = other;
        }
    }

    // ---- publish permutation ----
    __syncthreads();
    skeys[tid] = (uint32_t)(item & 0xFFFFFFFFu);   // inds[tid] = source packet
    __syncthreads();

    // ---- gather from smem, coalesced write ----
    float4* __restrict__ out4 = (float4*)(out + row * 8192);
    #pragma unroll
    for (int it = 0; it < 4; ++it) {
        int f = tid + it * 512;
        int p = f >> 2, w = f & 3;
        int src = (int)skeys[p];
        out4[f] = sdata[src * DPAD + w];
    }
}

extern "C" void kernel_launch(void* const* d_in, const int* in_sizes, int n_in,
                              void* d_out, int out_size)
{
    const float* z  = (const float*)d_in[0];
    float* out      = (float*)d_out;
    const int D = 8192;                 // n_packets(512) * packet(16)
    int B = in_sizes[0] / D;            // 4096
    sort_latent_kernel<<<B, 512>>>(z, out);
}